// round 5
// baseline (speedup 1.0000x reference)
#include <cuda_runtime.h>
#include <math.h>
#include <stdint.h>

#define BB 8192
#define DD 768
#define GH 384
#define EE 8
#define HH 3072
#define LN_EPS 1e-5f

// ---- scratch (static device globals) ----
__device__ float g_h[(size_t)BB * DD];                 // layernormed input
__device__ float g_g1[(size_t)BB * GH];                // gating hidden
__device__ float g_hid[(size_t)EE * BB * HH];          // expert hidden
__device__ float g_w[(size_t)BB * 2];
__device__ int   g_i[(size_t)BB * 2];

__device__ __forceinline__ float gelu_erf(float x) {
    return 0.5f * x * (1.0f + erff(x * 0.70710678118654752f));
}

__device__ __forceinline__ float to_tf32(float x) {
    float r;
    asm("cvt.rna.tf32.f32 %0, %1;" : "=f"(r) : "f"(x));
    return r;
}

__device__ __forceinline__ void mma_tf32(float c[4],
                                         uint32_t a0, uint32_t a1, uint32_t a2, uint32_t a3,
                                         uint32_t b0, uint32_t b1) {
    asm volatile(
        "mma.sync.aligned.m16n8k8.row.col.f32.tf32.tf32.f32 "
        "{%0,%1,%2,%3}, {%4,%5,%6,%7}, {%8,%9}, {%0,%1,%2,%3};"
        : "+f"(c[0]), "+f"(c[1]), "+f"(c[2]), "+f"(c[3])
        : "r"(a0), "r"(a1), "r"(a2), "r"(a3), "r"(b0), "r"(b1));
}

// ---------------------------------------------------------------------------
// K1: LayerNorm. one block per row.
// ---------------------------------------------------------------------------
__global__ void ln_kernel(const float* __restrict__ x,
                          const float* __restrict__ gamma,
                          const float* __restrict__ beta) {
    int b = blockIdx.x;
    const float* row = x + (size_t)b * DD;
    float s = 0.f, ss = 0.f;
    for (int d = threadIdx.x; d < DD; d += blockDim.x) {
        float v = row[d];
        s += v; ss += v * v;
    }
    #pragma unroll
    for (int o = 16; o; o >>= 1) {
        s  += __shfl_xor_sync(0xffffffffu, s, o);
        ss += __shfl_xor_sync(0xffffffffu, ss, o);
    }
    __shared__ float rs[8], rss[8];
    int w = threadIdx.x >> 5, l = threadIdx.x & 31;
    if (l == 0) { rs[w] = s; rss[w] = ss; }
    __syncthreads();
    if (w == 0) {
        s  = (l < (blockDim.x >> 5)) ? rs[l]  : 0.f;
        ss = (l < (blockDim.x >> 5)) ? rss[l] : 0.f;
        #pragma unroll
        for (int o = 4; o; o >>= 1) {
            s  += __shfl_xor_sync(0xffffffffu, s, o);
            ss += __shfl_xor_sync(0xffffffffu, ss, o);
        }
        if (l == 0) { rs[0] = s; rss[0] = ss; }
    }
    __syncthreads();
    float mu  = rs[0] * (1.0f / DD);
    float var = rss[0] * (1.0f / DD) - mu * mu;
    float inv = rsqrtf(var + LN_EPS);
    for (int d = threadIdx.x; d < DD; d += blockDim.x) {
        g_h[(size_t)b * DD + d] = (row[d] - mu) * inv * gamma[d] + beta[d];
    }
}

// ---------------------------------------------------------------------------
// fp32 SGEMM (kept for the gating hidden GEMM only; precision-sensitive path)
// ---------------------------------------------------------------------------
template <bool GELU>
__global__ __launch_bounds__(256, 2)
void sgemm(int M, int N, int K,
           const float* __restrict__ A, size_t aStride, int lda,
           const float* __restrict__ Bm, size_t bStride, int ldb,
           const float* __restrict__ bias, size_t biasStride,
           float* __restrict__ C, size_t cStride, int ldc) {
    constexpr int BM = 128, BN = 128, BK = 8, TM = 8, TN = 8;
    int e = blockIdx.z;
    A    += (size_t)e * aStride;
    Bm   += (size_t)e * bStride;
    bias += (size_t)e * biasStride;
    C    += (size_t)e * cStride;

    __shared__ float As[BK * BM];
    __shared__ float Bs[BK * BN];

    int tid = threadIdx.x;
    int innerRowA = tid >> 1, innerColA = tid & 1;
    int innerRowB = tid >> 5, innerColB = tid & 31;
    int threadRow = tid >> 4, threadCol = tid & 15;

    const float* Ablk = A + (size_t)blockIdx.y * BM * lda;
    const float* Bblk = Bm + (size_t)blockIdx.x * BN;

    float acc[TM][TN] = {};
    float regM[TM], regN[TN];

    for (int k0 = 0; k0 < K; k0 += BK) {
        float4 a4 = *(const float4*)(Ablk + (size_t)innerRowA * lda + k0 + innerColA * 4);
        As[(innerColA * 4 + 0) * BM + innerRowA] = a4.x;
        As[(innerColA * 4 + 1) * BM + innerRowA] = a4.y;
        As[(innerColA * 4 + 2) * BM + innerRowA] = a4.z;
        As[(innerColA * 4 + 3) * BM + innerRowA] = a4.w;
        *(float4*)(&Bs[innerRowB * BN + innerColB * 4]) =
            *(const float4*)(Bblk + (size_t)(k0 + innerRowB) * ldb + innerColB * 4);
        __syncthreads();
        #pragma unroll
        for (int k = 0; k < BK; k++) {
            #pragma unroll
            for (int i = 0; i < TM; i++) regM[i] = As[k * BM + threadRow * TM + i];
            #pragma unroll
            for (int j = 0; j < TN; j++) regN[j] = Bs[k * BN + threadCol * TN + j];
            #pragma unroll
            for (int i = 0; i < TM; i++)
                #pragma unroll
                for (int j = 0; j < TN; j++)
                    acc[i][j] += regM[i] * regN[j];
        }
        __syncthreads();
    }

    int colBase = blockIdx.x * BN + threadCol * TN;
    #pragma unroll
    for (int i = 0; i < TM; i++) {
        int row = blockIdx.y * BM + threadRow * TM + i;
        float* cp = C + (size_t)row * ldc + colBase;
        #pragma unroll
        for (int j = 0; j < TN; j += 4) {
            float4 v;
            v.x = acc[i][j + 0] + bias[colBase + j + 0];
            v.y = acc[i][j + 1] + bias[colBase + j + 1];
            v.z = acc[i][j + 2] + bias[colBase + j + 2];
            v.w = acc[i][j + 3] + bias[colBase + j + 3];
            if (GELU) {
                v.x = gelu_erf(v.x); v.y = gelu_erf(v.y);
                v.z = gelu_erf(v.z); v.w = gelu_erf(v.w);
            }
            *(float4*)(cp + j) = v;
        }
    }
}

// ---------------------------------------------------------------------------
// TF32 tensor-core GEMM: C[e] = (opt GELU)(A[e][M,K] @ B[e][K,N] + bias[e])
// 128x128x16 block tile, 8 warps of 64x32, mma.sync.m16n8k8 tf32.
// M,N,K divisible by 128/128/16 for all uses here.
// ---------------------------------------------------------------------------
template <bool GELU>
__global__ __launch_bounds__(256, 2)
void tf32gemm(int M, int N, int K,
              const float* __restrict__ A, size_t aStride, int lda,
              const float* __restrict__ Bm, size_t bStride, int ldb,
              const float* __restrict__ bias, size_t biasStride,
              float* __restrict__ C, size_t cStride, int ldc) {
    constexpr int BM = 128, BN = 128, BK = 16;
    constexpr int ASTR = BK + 4;   // 20 words: conflict-free fragment loads
    constexpr int BSTR = BN + 8;   // 136 words: conflict-free fragment loads

    int e = blockIdx.z;
    A    += (size_t)e * aStride;
    Bm   += (size_t)e * bStride;
    bias += (size_t)e * biasStride;
    C    += (size_t)e * cStride;

    __shared__ float As[BM][ASTR];
    __shared__ float Bs[BK][BSTR];

    const int tid  = threadIdx.x;
    const int warp = tid >> 5;
    const int lane = tid & 31;
    const int warpM = warp >> 2;       // 0..1  -> m offset *64
    const int warpN = warp & 3;        // 0..3  -> n offset *32

    const int blockM = blockIdx.y * BM;
    const int blockN = blockIdx.x * BN;

    // global load mapping
    const int arow = tid >> 2, ac4 = tid & 3;      // A: 2 float4 per thread
    const int brow = tid >> 5, bc4 = tid & 31;     // B: 2 float4 per thread

    const float* Ag = A + (size_t)(blockM + arow) * lda + ac4 * 4;
    const float* Bg = Bm + (size_t)brow * ldb + blockN + bc4 * 4;

    float4 pa0, pa1, pb0, pb1;

    // prologue: tile 0
    pa0 = *(const float4*)(Ag);
    pa1 = *(const float4*)(Ag + (size_t)64 * lda);
    pb0 = *(const float4*)(Bg);
    pb1 = *(const float4*)(Bg + (size_t)8 * ldb);

    float acc[4][4][4] = {};

    for (int k0 = 0; k0 < K; k0 += BK) {
        // convert + store current tile to smem
        {
            float4 t;
            t.x = to_tf32(pa0.x); t.y = to_tf32(pa0.y); t.z = to_tf32(pa0.z); t.w = to_tf32(pa0.w);
            *(float4*)(&As[arow][ac4 * 4]) = t;
            t.x = to_tf32(pa1.x); t.y = to_tf32(pa1.y); t.z = to_tf32(pa1.z); t.w = to_tf32(pa1.w);
            *(float4*)(&As[arow + 64][ac4 * 4]) = t;
            t.x = to_tf32(pb0.x); t.y = to_tf32(pb0.y); t.z = to_tf32(pb0.z); t.w = to_tf32(pb0.w);
            *(float4*)(&Bs[brow][bc4 * 4]) = t;
            t.x = to_tf32(pb1.x); t.y = to_tf32(pb1.y); t.z = to_tf32(pb1.z); t.w = to_tf32(pb1.w);
            *(float4*)(&Bs[brow + 8][bc4 * 4]) = t;
        }
        __syncthreads();

        // prefetch next tile
        if (k0 + BK < K) {
            const float* Agn = Ag + (k0 + BK);
            const float* Bgn = Bg + (size_t)(k0 + BK) * ldb;
            pa0 = *(const float4*)(Agn);
            pa1 = *(const float4*)(Agn + (size_t)64 * lda);
            pb0 = *(const float4*)(Bgn);
            pb1 = *(const float4*)(Bgn + (size_t)8 * ldb);
        }

        // compute 2 k-slices of 8
        const int r  = lane >> 2, c = lane & 3;
        const int col = lane >> 2, kk = lane & 3;
        #pragma unroll
        for (int ks = 0; ks < 2; ks++) {
            const int kb = ks * 8;
            uint32_t af[4][4];
            uint32_t bf[4][2];
            #pragma unroll
            for (int i = 0; i < 4; i++) {
                int mo = warpM * 64 + i * 16;
                af[i][0] = __float_as_uint(As[mo + r][kb + c]);
                af[i][1] = __float_as_uint(As[mo + r + 8][kb + c]);
                af[i][2] = __float_as_uint(As[mo + r][kb + c + 4]);
                af[i][3] = __float_as_uint(As[mo + r + 8][kb + c + 4]);
            }
            #pragma unroll
            for (int j = 0; j < 4; j++) {
                int no = warpN * 32 + j * 8;
                bf[j][0] = __float_as_uint(Bs[kb + kk][no + col]);
                bf[j][1] = __float_as_uint(Bs[kb + kk + 4][no + col]);
            }
            #pragma unroll
            for (int i = 0; i < 4; i++)
                #pragma unroll
                for (int j = 0; j < 4; j++)
                    mma_tf32(acc[i][j], af[i][0], af[i][1], af[i][2], af[i][3],
                             bf[j][0], bf[j][1]);
        }
        __syncthreads();
    }

    // epilogue
    const int r  = lane >> 2;
    const int cc = (lane & 3) * 2;
    #pragma unroll
    for (int i = 0; i < 4; i++) {
        int grow0 = blockM + warpM * 64 + i * 16 + r;
        int grow1 = grow0 + 8;
        #pragma unroll
        for (int j = 0; j < 4; j++) {
            int gcol = blockN + warpN * 32 + j * 8 + cc;
            float b0 = bias[gcol], b1 = bias[gcol + 1];
            float v0 = acc[i][j][0] + b0;
            float v1 = acc[i][j][1] + b1;
            float v2 = acc[i][j][2] + b0;
            float v3 = acc[i][j][3] + b1;
            if (GELU) {
                v0 = gelu_erf(v0); v1 = gelu_erf(v1);
                v2 = gelu_erf(v2); v3 = gelu_erf(v3);
            }
            float2 w0 = make_float2(v0, v1);
            float2 w1 = make_float2(v2, v3);
            *(float2*)(C + (size_t)grow0 * ldc + gcol) = w0;
            *(float2*)(C + (size_t)grow1 * ldc + gcol) = w1;
        }
    }
}

// ---------------------------------------------------------------------------
// K3: gating logits + softmax + top-2.
// ---------------------------------------------------------------------------
__global__ void gate_kernel(const float* __restrict__ gw2,
                            const float* __restrict__ gb2,
                            float* __restrict__ gate_out) {
    int warp = threadIdx.x >> 5, lane = threadIdx.x & 31;
    int b = blockIdx.x * 8 + warp;
    const float* g1 = g_g1 + (size_t)b * GH;
    float logit[EE];
    #pragma unroll
    for (int e = 0; e < EE; e++) {
        float acc = 0.f;
        for (int k = lane; k < GH; k += 32) acc += g1[k] * gw2[k * EE + e];
        #pragma unroll
        for (int o = 16; o; o >>= 1) acc += __shfl_xor_sync(0xffffffffu, acc, o);
        logit[e] = acc + gb2[e];
    }
    if (lane == 0) {
        float mx = logit[0];
        #pragma unroll
        for (int e = 1; e < EE; e++) mx = fmaxf(mx, logit[e]);
        float p[EE]; float sum = 0.f;
        #pragma unroll
        for (int e = 0; e < EE; e++) { p[e] = expf(logit[e] - mx); sum += p[e]; }
        float invs = 1.0f / sum;
        #pragma unroll
        for (int e = 0; e < EE; e++) {
            p[e] *= invs;
            gate_out[(size_t)b * EE + e] = p[e];
        }
        int i0 = 0;
        #pragma unroll
        for (int e = 1; e < EE; e++) if (p[e] > p[i0]) i0 = e;
        int i1 = (i0 == 0) ? 1 : 0;
        #pragma unroll
        for (int e = 0; e < EE; e++) if (e != i0 && p[e] > p[i1]) i1 = e;
        float w0 = p[i0], w1 = p[i1], s = w0 + w1;
        g_w[b * 2 + 0] = w0 / s;
        g_w[b * 2 + 1] = w1 / s;
        g_i[b * 2 + 0] = i0;
        g_i[b * 2 + 1] = i1;
    }
}

// ---------------------------------------------------------------------------
// K6: weighted combine of top-2 expert outputs.
// ---------------------------------------------------------------------------
__global__ void combine_kernel(const float* __restrict__ eo, float* __restrict__ out) {
    int b = blockIdx.x;
    int i0 = g_i[b * 2], i1 = g_i[b * 2 + 1];
    float w0 = g_w[b * 2], w1 = g_w[b * 2 + 1];
    const float* r0 = eo + (size_t)b * EE * DD + (size_t)i0 * DD;
    const float* r1 = eo + (size_t)b * EE * DD + (size_t)i1 * DD;
    float* o = out + (size_t)b * DD;
    for (int d = threadIdx.x; d < DD; d += blockDim.x)
        o[d] = w0 * r0[d] + w1 * r1[d];
}

// ---------------------------------------------------------------------------
extern "C" void kernel_launch(void* const* d_in, const int* in_sizes, int n_in,
                              void* d_out, int out_size) {
    const float* pooler   = (const float*)d_in[0];
    const float* ln_gamma = (const float*)d_in[1];
    const float* ln_beta  = (const float*)d_in[2];
    const float* gw1      = (const float*)d_in[3];
    const float* gb1      = (const float*)d_in[4];
    const float* gw2      = (const float*)d_in[5];
    const float* gb2      = (const float*)d_in[6];
    const float* ew1      = (const float*)d_in[7];
    const float* eb1      = (const float*)d_in[8];
    const float* ew2      = (const float*)d_in[9];
    const float* eb2      = (const float*)d_in[10];

    float* out        = (float*)d_out;
    float* out_result = out;                                  // [B, D]
    float* out_gate   = out + (size_t)BB * DD;                // [B, E]
    float* out_eo     = out_gate + (size_t)BB * EE;           // [B, E, D]

    float *h_ptr, *g1_ptr, *hid_ptr;
    cudaGetSymbolAddress((void**)&h_ptr, g_h);
    cudaGetSymbolAddress((void**)&g1_ptr, g_g1);
    cudaGetSymbolAddress((void**)&hid_ptr, g_hid);

    // 1) LayerNorm
    ln_kernel<<<BB, 256>>>(pooler, ln_gamma, ln_beta);

    // 2) gating hidden (fp32 for top-k stability): g1 = gelu(h @ gw1 + gb1)
    {
        dim3 grid(GH / 128, BB / 128, 1);
        sgemm<true><<<grid, 256>>>(BB, GH, DD,
                                   h_ptr, 0, DD,
                                   gw1, 0, GH,
                                   gb1, 0,
                                   g1_ptr, 0, GH);
    }

    // 3) gating logits + softmax + top2
    gate_kernel<<<BB / 8, 256>>>(gw2, gb2, out_gate);

    // 4) expert hidden (TF32 tensor): hid[e] = gelu(h @ ew1[e] + eb1[e])
    {
        dim3 grid(HH / 128, BB / 128, EE);
        tf32gemm<true><<<grid, 256>>>(BB, HH, DD,
                                      h_ptr, 0, DD,
                                      ew1, (size_t)DD * HH, HH,
                                      eb1, HH,
                                      hid_ptr, (size_t)BB * HH, HH);
    }

    // 5) expert outputs (TF32 tensor): eo[:,e,:] = hid[e] @ ew2[e] + eb2[e]
    {
        dim3 grid(DD / 128, BB / 128, EE);
        tf32gemm<false><<<grid, 256>>>(BB, DD, HH,
                                       hid_ptr, (size_t)BB * HH, HH,
                                       ew2, (size_t)HH * DD, DD,
                                       eb2, DD,
                                       out_eo, DD, EE * DD);
    }

    // 6) combine top-2
    combine_kernel<<<BB, 256>>>(out_eo, out_result);
}

// round 7
// speedup vs baseline: 2.3619x; 2.3619x over previous
#include <cuda_runtime.h>
#include <cuda_fp16.h>
#include <math.h>
#include <stdint.h>

#define BB 8192
#define DD 768
#define GH 384
#define EE 8
#define HH 3072
#define LN_EPS 1e-5f

// ---------------- scratch (static device globals) ----------------
__device__ float  g_h  [(size_t)BB * DD];          // LN output fp32 (gating path)
__device__ __half g_ht [(size_t)BB * DD];          // LN output, half (expert A)
__device__ float  g_g1 [(size_t)BB * GH];          // gating hidden
__device__ __half g_hid[(size_t)EE * BB * HH];     // expert hidden, half
__device__ __half g_w1t[(size_t)EE * HH * DD];     // ew1^T [e][H][D], half (K-major)
__device__ __half g_w2t[(size_t)EE * DD * HH];     // ew2^T [e][D][H], half (K-major)
__device__ float  g_w  [(size_t)BB * 2];
__device__ int    g_i  [(size_t)BB * 2];

// ---------------- helpers ----------------
__device__ __forceinline__ float gelu_erf(float x) {
    return 0.5f * x * (1.0f + erff(x * 0.70710678118654752f));
}
__device__ __forceinline__ uint32_t s2u(const void* p) {
    uint32_t a;
    asm("{ .reg .u64 t; cvta.to.shared.u64 t, %1; cvt.u32.u64 %0, t; }" : "=r"(a) : "l"(p));
    return a;
}

// XOR-swizzle on byte offset within a tile of 128B rows: chunk ^= (row & 7)
#define SWZ(off) ((uint32_t)(off) ^ (((uint32_t)(off) >> 3) & 0x70u))

#define CPA16(dst, src) \
    asm volatile("cp.async.cg.shared.global [%0], [%1], 16;" :: "r"(dst), "l"(src))
#define CPCOMMIT() asm volatile("cp.async.commit_group;" ::: "memory")
#define CPWAIT0()  asm volatile("cp.async.wait_group 0;" ::: "memory")
#define CPWAIT1()  asm volatile("cp.async.wait_group 1;" ::: "memory")

#define LDSM4(r, addr) \
    asm volatile("ldmatrix.sync.aligned.m8n8.x4.shared.b16 {%0,%1,%2,%3}, [%4];" \
        : "=r"((r)[0]), "=r"((r)[1]), "=r"((r)[2]), "=r"((r)[3]) : "r"(addr))

__device__ __forceinline__ void mma_f16(float c[4], const uint32_t a[4],
                                        uint32_t b0, uint32_t b1) {
    asm volatile(
        "mma.sync.aligned.m16n8k16.row.col.f32.f16.f16.f32 "
        "{%0,%1,%2,%3}, {%4,%5,%6,%7}, {%8,%9}, {%0,%1,%2,%3};"
        : "+f"(c[0]), "+f"(c[1]), "+f"(c[2]), "+f"(c[3])
        : "r"(a[0]), "r"(a[1]), "r"(a[2]), "r"(a[3]), "r"(b0), "r"(b1));
}

// ---------------------------------------------------------------------------
// K1: LayerNorm -> g_h (fp32) + g_ht (half)
// ---------------------------------------------------------------------------
__global__ void ln_kernel(const float* __restrict__ x,
                          const float* __restrict__ gamma,
                          const float* __restrict__ beta) {
    int b = blockIdx.x;
    const float* row = x + (size_t)b * DD;
    float s = 0.f, ss = 0.f;
    for (int d = threadIdx.x; d < DD; d += blockDim.x) {
        float v = row[d];
        s += v; ss += v * v;
    }
    #pragma unroll
    for (int o = 16; o; o >>= 1) {
        s  += __shfl_xor_sync(0xffffffffu, s, o);
        ss += __shfl_xor_sync(0xffffffffu, ss, o);
    }
    __shared__ float rs[8], rss[8];
    int w = threadIdx.x >> 5, l = threadIdx.x & 31;
    if (l == 0) { rs[w] = s; rss[w] = ss; }
    __syncthreads();
    if (w == 0) {
        s  = (l < (blockDim.x >> 5)) ? rs[l]  : 0.f;
        ss = (l < (blockDim.x >> 5)) ? rss[l] : 0.f;
        #pragma unroll
        for (int o = 4; o; o >>= 1) {
            s  += __shfl_xor_sync(0xffffffffu, s, o);
            ss += __shfl_xor_sync(0xffffffffu, ss, o);
        }
        if (l == 0) { rs[0] = s; rss[0] = ss; }
    }
    __syncthreads();
    float mu  = rs[0] * (1.0f / DD);
    float var = rss[0] * (1.0f / DD) - mu * mu;
    float inv = rsqrtf(var + LN_EPS);
    for (int d = threadIdx.x; d < DD; d += blockDim.x) {
        float v = (row[d] - mu) * inv * gamma[d] + beta[d];
        g_h [(size_t)b * DD + d] = v;
        g_ht[(size_t)b * DD + d] = __float2half_rn(v);
    }
}

// ---------------------------------------------------------------------------
// Weight transpose + fp32->half: src fp32 [e][R][C] -> dst half [e][C][R]
// ---------------------------------------------------------------------------
__global__ void transpose_h_kernel(const float* __restrict__ src,
                                   __half* __restrict__ dst, int R, int C) {
    __shared__ float t[32][33];
    int e = blockIdx.z;
    src += (size_t)e * R * C;
    dst += (size_t)e * R * C;
    int c0 = blockIdx.x * 32, r0 = blockIdx.y * 32;
    #pragma unroll
    for (int j = 0; j < 32; j += 8)
        t[threadIdx.y + j][threadIdx.x] =
            src[(size_t)(r0 + threadIdx.y + j) * C + c0 + threadIdx.x];
    __syncthreads();
    #pragma unroll
    for (int j = 0; j < 32; j += 8)
        dst[(size_t)(c0 + threadIdx.y + j) * R + r0 + threadIdx.x] =
            __float2half_rn(t[threadIdx.x][threadIdx.y + j]);
}

// ---------------------------------------------------------------------------
// fp32 SGEMM (gating hidden GEMM only; precision-sensitive path)
// ---------------------------------------------------------------------------
__global__ __launch_bounds__(256, 2)
void sgemm_gate(const float* __restrict__ A,
                const float* __restrict__ Bm,
                const float* __restrict__ bias,
                float* __restrict__ C) {
    constexpr int BM = 128, BN = 128, BK = 8, TM = 8, TN = 8;
    const int lda = DD, ldb = GH, ldc = GH, K = DD;

    __shared__ float As[BK * BM];
    __shared__ float Bs[BK * BN];

    int tid = threadIdx.x;
    int innerRowA = tid >> 1, innerColA = tid & 1;
    int innerRowB = tid >> 5, innerColB = tid & 31;
    int threadRow = tid >> 4, threadCol = tid & 15;

    const float* Ablk = A + (size_t)blockIdx.y * BM * lda;
    const float* Bblk = Bm + (size_t)blockIdx.x * BN;

    float acc[TM][TN] = {};
    float regM[TM], regN[TN];

    for (int k0 = 0; k0 < K; k0 += BK) {
        float4 a4 = *(const float4*)(Ablk + (size_t)innerRowA * lda + k0 + innerColA * 4);
        As[(innerColA * 4 + 0) * BM + innerRowA] = a4.x;
        As[(innerColA * 4 + 1) * BM + innerRowA] = a4.y;
        As[(innerColA * 4 + 2) * BM + innerRowA] = a4.z;
        As[(innerColA * 4 + 3) * BM + innerRowA] = a4.w;
        *(float4*)(&Bs[innerRowB * BN + innerColB * 4]) =
            *(const float4*)(Bblk + (size_t)(k0 + innerRowB) * ldb + innerColB * 4);
        __syncthreads();
        #pragma unroll
        for (int k = 0; k < BK; k++) {
            #pragma unroll
            for (int i = 0; i < TM; i++) regM[i] = As[k * BM + threadRow * TM + i];
            #pragma unroll
            for (int j = 0; j < TN; j++) regN[j] = Bs[k * BN + threadCol * TN + j];
            #pragma unroll
            for (int i = 0; i < TM; i++)
                #pragma unroll
                for (int j = 0; j < TN; j++)
                    acc[i][j] += regM[i] * regN[j];
        }
        __syncthreads();
    }

    int colBase = blockIdx.x * BN + threadCol * TN;
    #pragma unroll
    for (int i = 0; i < TM; i++) {
        int row = blockIdx.y * BM + threadRow * TM + i;
        float* cp = C + (size_t)row * ldc + colBase;
        #pragma unroll
        for (int j = 0; j < TN; j += 4) {
            float4 v;
            v.x = gelu_erf(acc[i][j + 0] + bias[colBase + j + 0]);
            v.y = gelu_erf(acc[i][j + 1] + bias[colBase + j + 1]);
            v.z = gelu_erf(acc[i][j + 2] + bias[colBase + j + 2]);
            v.w = gelu_erf(acc[i][j + 3] + bias[colBase + j + 3]);
            *(float4*)(cp + j) = v;
        }
    }
}

// ---------------------------------------------------------------------------
// fp16 tensor-core GEMM (mma.sync m16n8k16 + ldmatrix + cp.async 3-stage).
// A half [e][M][K] row-major; Bt half [e][N][K] K-major. fp32 accumulate.
// CTA tile 128x128, BK=64 halfs (=128B rows, SW128 XOR swizzle).
// 8 warps: warp tile 64x32 (warpM 0-1, warpN 0-3).
// EOUT: write fp32 to out_eo[(row*EE+e)*DD+col]; else half to g_hid.
// ---------------------------------------------------------------------------
template <int K, int N, bool GELU, bool EOUT>
__global__ __launch_bounds__(256, 2)
void hgemm(const __half* __restrict__ A, size_t aStride,
           const __half* __restrict__ Bt,
           const float* __restrict__ bias,
           void* __restrict__ Cout) {
    constexpr int BK = 64;                 // halfs per K-tile
    constexpr int NIT = K / BK;
    constexpr int ABYTES = 128 * 128;      // 16 KB per operand tile
    constexpr int STAGE_BYTES = 2 * ABYTES;
    constexpr int STAGES = 3;

    extern __shared__ char smem[];
    const int e  = blockIdx.z;
    const int n0 = blockIdx.x * 128;
    const int m0 = blockIdx.y * 128;
    A    += (size_t)e * aStride;
    Bt   += (size_t)e * (size_t)N * K;
    bias += (size_t)e * N;

    const int tid   = threadIdx.x;
    const int warp  = tid >> 5;
    const int lane  = tid & 31;
    const int warpM = warp >> 2;
    const int warpN = warp & 3;

    const uint32_t sbase = s2u(smem);

    auto load_stage = [&](int s, int k0) {
        uint32_t aB = sbase + (uint32_t)s * STAGE_BYTES;
        uint32_t bB = aB + ABYTES;
        #pragma unroll
        for (int t = 0; t < 4; t++) {
            int id = tid + t * 256;
            int row = id >> 3, c = id & 7;
            const __half* src = A + (size_t)(m0 + row) * K + k0 + c * 8;
            CPA16(aB + SWZ(row * 128 + c * 16), src);
        }
        #pragma unroll
        for (int t = 0; t < 4; t++) {
            int id = tid + t * 256;
            int row = id >> 3, c = id & 7;
            const __half* src = Bt + (size_t)(n0 + row) * K + k0 + c * 8;
            CPA16(bB + SWZ(row * 128 + c * 16), src);
        }
    };

    load_stage(0, 0);   CPCOMMIT();
    load_stage(1, BK);  CPCOMMIT();

    float acc[4][4][4] = {};

    for (int i = 0; i < NIT; i++) {
        if (i + 1 < NIT) { CPWAIT1(); } else { CPWAIT0(); }
        __syncthreads();

        if (i + 2 < NIT) {
            load_stage((i + 2) % STAGES, (i + 2) * BK);
            CPCOMMIT();
        }

        const int s = i % STAGES;
        const uint32_t aB = sbase + (uint32_t)s * STAGE_BYTES;
        const uint32_t bB = aB + ABYTES;

        #pragma unroll
        for (int ks = 0; ks < 4; ks++) {
            uint32_t afr[4][4], bfr[2][4];
            const int c = ks * 2 + (lane >> 4);
            #pragma unroll
            for (int ii = 0; ii < 4; ii++) {
                int row = warpM * 64 + ii * 16 + (lane & 15);
                LDSM4(afr[ii], aB + SWZ(row * 128 + c * 16));
            }
            #pragma unroll
            for (int jp = 0; jp < 2; jp++) {
                int row = warpN * 32 + jp * 16 + (lane & 15);
                LDSM4(bfr[jp], bB + SWZ(row * 128 + c * 16));
            }
            #pragma unroll
            for (int ii = 0; ii < 4; ii++) {
                #pragma unroll
                for (int jp = 0; jp < 2; jp++) {
                    mma_f16(acc[ii][jp * 2 + 0], afr[ii], bfr[jp][0], bfr[jp][2]);
                    mma_f16(acc[ii][jp * 2 + 1], afr[ii], bfr[jp][1], bfr[jp][3]);
                }
            }
        }
        // no trailing sync: next-iter top sync orders reuse
    }

    // epilogue
    const int r  = lane >> 2;
    const int c2 = (lane & 3) * 2;
    #pragma unroll
    for (int ii = 0; ii < 4; ii++) {
        int row0 = m0 + warpM * 64 + ii * 16 + r;
        int row1 = row0 + 8;
        #pragma unroll
        for (int j = 0; j < 4; j++) {
            int gcol = n0 + warpN * 32 + j * 8 + c2;
            float b0 = bias[gcol], b1 = bias[gcol + 1];
            float v0 = acc[ii][j][0] + b0;
            float v1 = acc[ii][j][1] + b1;
            float v2 = acc[ii][j][2] + b0;
            float v3 = acc[ii][j][3] + b1;
            if (GELU) {
                v0 = gelu_erf(v0); v1 = gelu_erf(v1);
                v2 = gelu_erf(v2); v3 = gelu_erf(v3);
            }
            if (EOUT) {
                float* C = (float*)Cout;
                *(float2*)(C + ((size_t)row0 * EE + e) * DD + gcol) = make_float2(v0, v1);
                *(float2*)(C + ((size_t)row1 * EE + e) * DD + gcol) = make_float2(v2, v3);
            } else {
                __half* C = (__half*)Cout;
                *(__half2*)(C + ((size_t)e * BB + row0) * (size_t)N + gcol) =
                    __floats2half2_rn(v0, v1);
                *(__half2*)(C + ((size_t)e * BB + row1) * (size_t)N + gcol) =
                    __floats2half2_rn(v2, v3);
            }
        }
    }
}

// ---------------------------------------------------------------------------
// K3: gating logits + softmax + top-2
// ---------------------------------------------------------------------------
__global__ void gate_kernel(const float* __restrict__ gw2,
                            const float* __restrict__ gb2,
                            float* __restrict__ gate_out) {
    int warp = threadIdx.x >> 5, lane = threadIdx.x & 31;
    int b = blockIdx.x * 8 + warp;
    const float* g1 = g_g1 + (size_t)b * GH;
    float logit[EE];
    #pragma unroll
    for (int e = 0; e < EE; e++) {
        float acc = 0.f;
        for (int k = lane; k < GH; k += 32) acc += g1[k] * gw2[k * EE + e];
        #pragma unroll
        for (int o = 16; o; o >>= 1) acc += __shfl_xor_sync(0xffffffffu, acc, o);
        logit[e] = acc + gb2[e];
    }
    if (lane == 0) {
        float mx = logit[0];
        #pragma unroll
        for (int e = 1; e < EE; e++) mx = fmaxf(mx, logit[e]);
        float p[EE]; float sum = 0.f;
        #pragma unroll
        for (int e = 0; e < EE; e++) { p[e] = expf(logit[e] - mx); sum += p[e]; }
        float invs = 1.0f / sum;
        #pragma unroll
        for (int e = 0; e < EE; e++) {
            p[e] *= invs;
            gate_out[(size_t)b * EE + e] = p[e];
        }
        int i0 = 0;
        #pragma unroll
        for (int e = 1; e < EE; e++) if (p[e] > p[i0]) i0 = e;
        int i1 = (i0 == 0) ? 1 : 0;
        #pragma unroll
        for (int e = 0; e < EE; e++) if (e != i0 && p[e] > p[i1]) i1 = e;
        float w0 = p[i0], w1 = p[i1], s = w0 + w1;
        g_w[b * 2 + 0] = w0 / s;
        g_w[b * 2 + 1] = w1 / s;
        g_i[b * 2 + 0] = i0;
        g_i[b * 2 + 1] = i1;
    }
}

// ---------------------------------------------------------------------------
// K6: weighted combine of top-2 expert outputs
// ---------------------------------------------------------------------------
__global__ void combine_kernel(const float* __restrict__ eo, float* __restrict__ out) {
    int b = blockIdx.x;
    int i0 = g_i[b * 2], i1 = g_i[b * 2 + 1];
    float w0 = g_w[b * 2], w1 = g_w[b * 2 + 1];
    const float* r0 = eo + (size_t)b * EE * DD + (size_t)i0 * DD;
    const float* r1 = eo + (size_t)b * EE * DD + (size_t)i1 * DD;
    float* o = out + (size_t)b * DD;
    for (int d = threadIdx.x; d < DD; d += blockDim.x)
        o[d] = w0 * r0[d] + w1 * r1[d];
}

// ---------------------------------------------------------------------------
extern "C" void kernel_launch(void* const* d_in, const int* in_sizes, int n_in,
                              void* d_out, int out_size) {
    const float* pooler   = (const float*)d_in[0];
    const float* ln_gamma = (const float*)d_in[1];
    const float* ln_beta  = (const float*)d_in[2];
    const float* gw1      = (const float*)d_in[3];
    const float* gb1      = (const float*)d_in[4];
    const float* gw2      = (const float*)d_in[5];
    const float* gb2      = (const float*)d_in[6];
    const float* ew1      = (const float*)d_in[7];
    const float* eb1      = (const float*)d_in[8];
    const float* ew2      = (const float*)d_in[9];
    const float* eb2      = (const float*)d_in[10];

    float* out        = (float*)d_out;
    float* out_result = out;                          // [B, D]
    float* out_gate   = out + (size_t)BB * DD;        // [B, E]
    float* out_eo     = out_gate + (size_t)BB * EE;   // [B, E, D]

    float  *h_ptr, *g1_ptr;
    __half *ht_ptr, *hid_ptr, *w1t_ptr, *w2t_ptr;
    cudaGetSymbolAddress((void**)&h_ptr,   g_h);
    cudaGetSymbolAddress((void**)&ht_ptr,  g_ht);
    cudaGetSymbolAddress((void**)&g1_ptr,  g_g1);
    cudaGetSymbolAddress((void**)&hid_ptr, g_hid);
    cudaGetSymbolAddress((void**)&w1t_ptr, g_w1t);
    cudaGetSymbolAddress((void**)&w2t_ptr, g_w2t);

    const int SMEM = 3 * 32768;   // 96 KB dynamic
    cudaFuncSetAttribute(hgemm<DD, HH, true,  false>,
                         cudaFuncAttributeMaxDynamicSharedMemorySize, SMEM);
    cudaFuncSetAttribute(hgemm<HH, DD, false, true>,
                         cudaFuncAttributeMaxDynamicSharedMemorySize, SMEM);

    // 1) LayerNorm (fp32 + half copy)
    ln_kernel<<<BB, 256>>>(pooler, ln_gamma, ln_beta);

    // 1b) weight transposes to K-major half
    {
        dim3 blk(32, 8);
        transpose_h_kernel<<<dim3(HH / 32, DD / 32, EE), blk>>>(ew1, w1t_ptr, DD, HH);
        transpose_h_kernel<<<dim3(DD / 32, HH / 32, EE), blk>>>(ew2, w2t_ptr, HH, DD);
    }

    // 2) gating hidden (fp32): g1 = gelu(h @ gw1 + gb1)
    sgemm_gate<<<dim3(GH / 128, BB / 128, 1), 256>>>(h_ptr, gw1, gb1, g1_ptr);

    // 3) gating logits + softmax + top2
    gate_kernel<<<BB / 8, 256>>>(gw2, gb2, out_gate);

    // 4) expert hidden (fp16 mma): hid[e] = half(gelu(h @ ew1[e] + eb1[e]))
    hgemm<DD, HH, true, false><<<dim3(HH / 128, BB / 128, EE), 256, SMEM>>>(
        ht_ptr, 0, w1t_ptr, eb1, hid_ptr);

    // 5) expert outputs (fp16 mma): eo[:,e,:] = hid[e] @ ew2[e] + eb2[e]
    hgemm<HH, DD, false, true><<<dim3(DD / 128, BB / 128, EE), 256, SMEM>>>(
        hid_ptr, (size_t)BB * HH, w2t_ptr, eb2, out_eo);

    // 6) combine top-2
    combine_kernel<<<BB, 256>>>(out_eo, out_result);
}